// round 9
// baseline (speedup 1.0000x reference)
#include <cuda_runtime.h>
#include <cuda_bf16.h>
#include <cstdint>

// Problem constants
#define BATCH   4
#define T_TXT   2048
#define T_IMG   8
#define N_LAT   64
#define DIM     2048
#define DIM_VIS 1024
#define HEADS   8
#define DIM_HEAD 64
#define INNER   (HEADS * DIM_HEAD)      // 512
#define ROWS    (BATCH * T_TXT)         // 8192
#define KVROWS  (BATCH * T_IMG * N_LAT) // 2048
#define LN_EPS  1e-5f

// ---------------- scratch (static device, no allocs) ----------------
__device__ float g_xn[ROWS * DIM];
__device__ float g_q [ROWS * INNER];
__device__ float g_kv[KVROWS * 2 * INNER];
__device__ float g_ao[ROWS * INNER];
__device__ float g_wq_t [DIM * INNER];
__device__ float g_wkv_t[DIM_VIS * 2 * INNER];
__device__ float g_wout_t[INNER * DIM];
__device__ float g_media_t[KVROWS * DIM_VIS];
__device__ int   g_qlist[BATCH][9][T_TXT];
__device__ int   g_qcount[BATCH][9];

__device__ __forceinline__ uint32_t f2tf32(float f) {
    uint32_t r;
    asm("cvt.rna.tf32.f32 %0, %1;" : "=r"(r) : "f"(f));
    return r;
}
__device__ __forceinline__ float rnd_tf32(float f) { return __uint_as_float(f2tf32(f)); }
__device__ __forceinline__ uint32_t smem_u32(const void* p) {
    uint32_t a;
    asm("{ .reg .u64 t; cvta.to.shared.u64 t, %1; cvt.u32.u64 %0, t; }" : "=r"(a) : "l"(p));
    return a;
}

#define CP_ASYNC16(dst, src) \
    asm volatile("cp.async.cg.shared.global [%0], [%1], 16;" :: "r"(dst), "l"(src))
#define CP_COMMIT() asm volatile("cp.async.commit_group;" ::: "memory")
#define CP_WAIT1()  asm volatile("cp.async.wait_group 1;" ::: "memory")

// ---------------- cp.async 3-stage pipelined TF32 GEMM ----------------
// C[M,N] = A[M,K] @ B[K,N], row-major fp32 PRE-ROUNDED to tf32 (rna).
// Block 128x128, KT=32, 256 threads (8 warps), warp tile 64x32, 3 stages.
#define KT 32
#define PA 36                 // floats per A smem row (128 rows)
#define PB 136                // floats per B smem row (32 rows)
#define A_STG_BYTES (128 * PA * 4)   // 18432
#define B_STG_BYTES (KT * PB * 4)    // 17408
#define STAGES 3
#define SMEM_BYTES (STAGES * (A_STG_BYTES + B_STG_BYTES))  // 107520

__global__ __launch_bounds__(256, 2) void tf32gemm_pipe(const float* __restrict__ A,
                                                        const float* __restrict__ B,
                                                        float* __restrict__ C,
                                                        int M, int N, int K) {
    extern __shared__ char smem[];
    const uint32_t sb = smem_u32(smem);
    const int tid = threadIdx.x;
    const int lane = tid & 31, warp = tid >> 5;
    const int tq = lane & 3, tg = lane >> 2;
    const int wm = (warp >> 2) * 64;   // 0/64
    const int wn = (warp & 3) * 32;    // 0/32/64/96

    const int mblk = blockIdx.y * 128;
    const int nblk = blockIdx.x * 128;
    const float* Ab = A + (size_t)mblk * K;
    const float* Bb = B + nblk;

    float acc[4][4][4];
    #pragma unroll
    for (int mf = 0; mf < 4; mf++)
        #pragma unroll
        for (int nf = 0; nf < 4; nf++)
            #pragma unroll
            for (int i = 0; i < 4; i++) acc[mf][nf][i] = 0.f;

    const int nK = K / KT;

    auto issue = [&](int s, int c) {
        const uint32_t sa = sb + s * (A_STG_BYTES + B_STG_BYTES);
        const uint32_t sB = sa + A_STG_BYTES;
        const int k0 = c * KT;
        #pragma unroll
        for (int i = 0; i < 4; i++) {           // A: 4 chunks/thread
            int id = tid + i * 256;             // 0..1023
            int row = id >> 3, c4 = id & 7;
            CP_ASYNC16(sa + row * (PA * 4) + c4 * 16,
                       Ab + (size_t)row * K + k0 + c4 * 4);
        }
        #pragma unroll
        for (int i = 0; i < 4; i++) {           // B: 4 chunks/thread
            int id = tid + i * 256;
            int row = id >> 5, c4 = id & 31;
            CP_ASYNC16(sB + row * (PB * 4) + c4 * 16,
                       Bb + (size_t)(k0 + row) * N + c4 * 4);
        }
    };

    issue(0, 0); CP_COMMIT();
    if (nK > 1) issue(1, 1);
    CP_COMMIT();

    int buf = 0;
    for (int c = 0; c < nK; c++) {
        CP_WAIT1();
        __syncthreads();
        if (c + 2 < nK) issue((c + 2) % STAGES, c + 2);
        CP_COMMIT();

        const float* As = (const float*)(smem + buf * (A_STG_BYTES + B_STG_BYTES));
        const float* Bs = (const float*)(smem + buf * (A_STG_BYTES + B_STG_BYTES) + A_STG_BYTES);

        #pragma unroll
        for (int ks = 0; ks < KT; ks += 8) {
            uint32_t af[4][4], bf[4][2];
            #pragma unroll
            for (int mf = 0; mf < 4; mf++) {
                const int m0 = wm + mf * 16 + tg;
                af[mf][0] = __float_as_uint(As[m0 * PA + ks + tq]);
                af[mf][1] = __float_as_uint(As[(m0 + 8) * PA + ks + tq]);
                af[mf][2] = __float_as_uint(As[m0 * PA + ks + tq + 4]);
                af[mf][3] = __float_as_uint(As[(m0 + 8) * PA + ks + tq + 4]);
            }
            #pragma unroll
            for (int nf = 0; nf < 4; nf++) {
                bf[nf][0] = __float_as_uint(Bs[(ks + tq) * PB + wn + nf * 8 + tg]);
                bf[nf][1] = __float_as_uint(Bs[(ks + tq + 4) * PB + wn + nf * 8 + tg]);
            }
            #pragma unroll
            for (int mf = 0; mf < 4; mf++)
                #pragma unroll
                for (int nf = 0; nf < 4; nf++) {
                    asm volatile(
                        "mma.sync.aligned.m16n8k8.row.col.f32.tf32.tf32.f32 "
                        "{%0,%1,%2,%3}, {%4,%5,%6,%7}, {%8,%9}, {%0,%1,%2,%3};"
                        : "+f"(acc[mf][nf][0]), "+f"(acc[mf][nf][1]),
                          "+f"(acc[mf][nf][2]), "+f"(acc[mf][nf][3])
                        : "r"(af[mf][0]), "r"(af[mf][1]), "r"(af[mf][2]), "r"(af[mf][3]),
                          "r"(bf[nf][0]), "r"(bf[nf][1]));
                }
        }
        __syncthreads();
        buf = (buf + 1) % STAGES;
    }

    // epilogue
    #pragma unroll
    for (int mf = 0; mf < 4; mf++) {
        const int row0 = mblk + wm + mf * 16 + tg;
        #pragma unroll
        for (int nf = 0; nf < 4; nf++) {
            const int col = nblk + wn + nf * 8 + 2 * tq;
            *(float2*)(C + (size_t)row0 * N + col) =
                make_float2(acc[mf][nf][0], acc[mf][nf][1]);
            *(float2*)(C + (size_t)(row0 + 8) * N + col) =
                make_float2(acc[mf][nf][2], acc[mf][nf][3]);
        }
    }
}

// ---------------- tf32 pre-round (rna) for weights/media ----------------
__global__ __launch_bounds__(256) void cvt_tf32_kernel(const float* __restrict__ in,
                                                       float* __restrict__ out, int n4) {
    int i = blockIdx.x * 256 + threadIdx.x;
    if (i < n4) {
        float4 v = ((const float4*)in)[i];
        v.x = rnd_tf32(v.x); v.y = rnd_tf32(v.y); v.z = rnd_tf32(v.z); v.w = rnd_tf32(v.w);
        ((float4*)out)[i] = v;
    }
}

// ---------------- LayerNorm (single pass, tf32-rounded output) ----------------
__global__ __launch_bounds__(256) void ln_kernel(const float* __restrict__ x,
                                                 const float* __restrict__ gamma,
                                                 const float* __restrict__ beta) {
    const int row = blockIdx.x;
    const float4* xr = (const float4*)(x + (size_t)row * DIM);
    float4* out = (float4*)(g_xn + (size_t)row * DIM);
    const int tid = threadIdx.x;

    __shared__ float reds[256], redq[256];
    float s = 0.f, sq = 0.f;
    #pragma unroll
    for (int c = tid; c < DIM / 4; c += 256) {
        float4 v = xr[c];
        s  += v.x + v.y + v.z + v.w;
        sq += v.x * v.x + v.y * v.y + v.z * v.z + v.w * v.w;
    }
    reds[tid] = s; redq[tid] = sq; __syncthreads();
    for (int o = 128; o > 0; o >>= 1) {
        if (tid < o) { reds[tid] += reds[tid + o]; redq[tid] += redq[tid + o]; }
        __syncthreads();
    }
    const float mu = reds[0] * (1.0f / DIM);
    const float var = redq[0] * (1.0f / DIM) - mu * mu;
    const float rstd = rsqrtf(var + LN_EPS);

    const float4* g4 = (const float4*)gamma;
    const float4* b4 = (const float4*)beta;
    #pragma unroll
    for (int c = tid; c < DIM / 4; c += 256) {
        float4 v = xr[c], g = g4[c], bb = b4[c], o4;
        o4.x = rnd_tf32((v.x - mu) * rstd * g.x + bb.x);
        o4.y = rnd_tf32((v.y - mu) * rstd * g.y + bb.y);
        o4.z = rnd_tf32((v.z - mu) * rstd * g.z + bb.z);
        o4.w = rnd_tf32((v.w - mu) * rstd * g.w + bb.w);
        out[c] = o4;
    }
}

// ---------------- parallel build of per-(b,tt) query lists ----------------
__global__ __launch_bounds__(256) void build_lists2(const int* __restrict__ locs) {
    const int b = blockIdx.x;
    const int tid = threadIdx.x;
    __shared__ int ssum[256];
    __shared__ int cnt[9];

    const int base = tid * 8;
    int v[8];
    int s = 0;
    #pragma unroll
    for (int j = 0; j < 8; j++) { v[j] = locs[b * T_TXT + base + j]; s += v[j]; }
    ssum[tid] = s;
    if (tid < 9) cnt[tid] = 0;
    __syncthreads();
    for (int off = 1; off < 256; off <<= 1) {
        int t = (tid >= off) ? ssum[tid - off] : 0;
        __syncthreads();
        ssum[tid] += t;
        __syncthreads();
    }
    int run = ssum[tid] - s;
    #pragma unroll
    for (int j = 0; j < 8; j++) {
        run += v[j];
        int p = atomicAdd(&cnt[run], 1);
        g_qlist[b][run][p] = base + j;
    }
    __syncthreads();
    if (tid < 9) g_qcount[b][tid] = cnt[tid];
}

// ---------------- masked chunk attention (tf32-rounded output) ----------------
__global__ __launch_bounds__(256) void attn_kernel() {
    const int blk = blockIdx.x;                 // b*72 + h*9 + tt
    const int b = blk / 72;
    const int h = (blk / 9) % 8;
    const int tt = blk % 9;
    const int cnt = g_qcount[b][tt];
    if (cnt == 0) return;

    const int lane = threadIdx.x & 31;
    const int warp = threadIdx.x >> 5;

    if (tt == 0) {
        for (int qi = warp; qi < cnt; qi += 8) {
            int i = g_qlist[b][0][qi];
            float* dst = g_ao + (size_t)(b * T_TXT + i) * INNER + h * DIM_HEAD;
            dst[lane] = 0.f; dst[lane + 32] = 0.f;
        }
        return;
    }

    __shared__ float ksh[64][65];
    __shared__ float vsh[64][65];
    const int base = b * 512 + (tt - 1) * 64;
    for (int idx = threadIdx.x; idx < 4096; idx += 256) {
        int r = idx >> 6, c = idx & 63;
        const float* kvr = g_kv + (size_t)(base + r) * (2 * INNER);
        ksh[r][c] = kvr[h * DIM_HEAD + c];
        vsh[r][c] = kvr[INNER + h * DIM_HEAD + c];
    }
    __syncthreads();

    const float scale = 0.125f;
    for (int qi = warp; qi < cnt; qi += 8) {
        const int i = g_qlist[b][tt][qi];
        const float* qr = g_q + (size_t)(b * T_TXT + i) * INNER + h * DIM_HEAD;
        const float q0 = qr[lane] * scale;
        const float q1 = qr[lane + 32] * scale;

        float s0 = 0.f, s1 = 0.f;
        #pragma unroll
        for (int d = 0; d < 32; d++) {
            float qd = __shfl_sync(0xffffffffu, q0, d);
            s0 += qd * ksh[lane][d];
            s1 += qd * ksh[lane + 32][d];
        }
        #pragma unroll
        for (int d = 0; d < 32; d++) {
            float qd = __shfl_sync(0xffffffffu, q1, d);
            s0 += qd * ksh[lane][d + 32];
            s1 += qd * ksh[lane + 32][d + 32];
        }
        float m = fmaxf(s0, s1);
        #pragma unroll
        for (int o = 16; o > 0; o >>= 1) m = fmaxf(m, __shfl_xor_sync(0xffffffffu, m, o));
        float p0 = __expf(s0 - m), p1 = __expf(s1 - m);
        float sum = p0 + p1;
        #pragma unroll
        for (int o = 16; o > 0; o >>= 1) sum += __shfl_xor_sync(0xffffffffu, sum, o);
        const float inv = 1.f / sum;
        p0 *= inv; p1 *= inv;

        float o0 = 0.f, o1 = 0.f;
        #pragma unroll
        for (int j = 0; j < 32; j++) {
            float pa = __shfl_sync(0xffffffffu, p0, j);
            float pb = __shfl_sync(0xffffffffu, p1, j);
            o0 += pa * vsh[j][lane]      + pb * vsh[j + 32][lane];
            o1 += pa * vsh[j][lane + 32] + pb * vsh[j + 32][lane + 32];
        }
        float* dst = g_ao + (size_t)(b * T_TXT + i) * INNER + h * DIM_HEAD;
        dst[lane]      = rnd_tf32(o0);
        dst[lane + 32] = rnd_tf32(o1);
    }
}

// ---------------- launch ----------------
// Order chosen so the 4th launch is the big q-GEMM (for ncu's fixed capture slot),
// while preserving all data dependencies.
extern "C" void kernel_launch(void* const* d_in, const int* in_sizes, int n_in,
                              void* d_out, int out_size) {
    const float* x     = (const float*)d_in[0];
    const float* media = (const float*)d_in[1];
    const int*   locs  = (const int*)d_in[2];
    const float* gamma = (const float*)d_in[3];
    const float* beta  = (const float*)d_in[4];
    const float* Wq    = (const float*)d_in[5];
    const float* Wkv   = (const float*)d_in[6];
    const float* Wout  = (const float*)d_in[7];
    float*       out   = (float*)d_out;

    float *p_xn, *p_q, *p_kv, *p_ao, *p_wq, *p_wkv, *p_wout, *p_media;
    cudaGetSymbolAddress((void**)&p_xn, g_xn);
    cudaGetSymbolAddress((void**)&p_q,  g_q);
    cudaGetSymbolAddress((void**)&p_kv, g_kv);
    cudaGetSymbolAddress((void**)&p_ao, g_ao);
    cudaGetSymbolAddress((void**)&p_wq, g_wq_t);
    cudaGetSymbolAddress((void**)&p_wkv, g_wkv_t);
    cudaGetSymbolAddress((void**)&p_wout, g_wout_t);
    cudaGetSymbolAddress((void**)&p_media, g_media_t);

    cudaFuncSetAttribute(tf32gemm_pipe, cudaFuncAttributeMaxDynamicSharedMemorySize, SMEM_BYTES);

    // 1. Wq round
    cvt_tf32_kernel<<<(DIM * INNER / 4) / 256, 256>>>(Wq, p_wq, DIM * INNER / 4);
    // 2. LayerNorm (tf32-rounded output)
    ln_kernel<<<ROWS, 256>>>(x, gamma, beta);
    // 3. query grouping by text_time
    build_lists2<<<BATCH, 256>>>(locs);
    // 4. q = xn @ Wq             (8192 x 512 x 2048)  <-- profiled slot
    tf32gemm_pipe<<<dim3(INNER / 128, ROWS / 128), 256, SMEM_BYTES>>>(
        p_xn, p_wq, p_q, ROWS, INNER, DIM);
    // 5-6. Wkv + media round
    cvt_tf32_kernel<<<(DIM_VIS * 2 * INNER / 4) / 256, 256>>>(Wkv, p_wkv, DIM_VIS * 2 * INNER / 4);
    cvt_tf32_kernel<<<(KVROWS * DIM_VIS / 4) / 256, 256>>>(media, p_media, KVROWS * DIM_VIS / 4);
    // 7. kv = media_flat @ Wkv   (2048 x 1024 x 1024)
    tf32gemm_pipe<<<dim3((2 * INNER) / 128, KVROWS / 128), 256, SMEM_BYTES>>>(
        p_media, p_wkv, p_kv, KVROWS, 2 * INNER, DIM_VIS);
    // 8. masked chunk attention (tf32-rounded output)
    attn_kernel<<<BATCH * HEADS * 9, 256>>>();
    // 9. Wout round
    cvt_tf32_kernel<<<(INNER * DIM / 4) / 256, 256>>>(Wout, p_wout, INNER * DIM / 4);
    // 10. out = ao @ Wout        (8192 x 2048 x 512)
    tf32gemm_pipe<<<dim3(DIM / 128, ROWS / 128), 256, SMEM_BYTES>>>(
        p_ao, p_wout, out, ROWS, DIM, INNER);
}

// round 10
// speedup vs baseline: 1.6453x; 1.6453x over previous
#include <cuda_runtime.h>
#include <cuda_bf16.h>
#include <cstdint>

// Problem constants
#define BATCH   4
#define T_TXT   2048
#define T_IMG   8
#define N_LAT   64
#define DIM     2048
#define DIM_VIS 1024
#define HEADS   8
#define DIM_HEAD 64
#define INNER   (HEADS * DIM_HEAD)      // 512
#define ROWS    (BATCH * T_TXT)         // 8192
#define KVROWS  (BATCH * T_IMG * N_LAT) // 2048
#define LN_EPS  1e-5f

// ---------------- scratch (static device, no allocs) ----------------
__device__ float g_xn[ROWS * DIM];
__device__ float g_q [ROWS * INNER];
__device__ float g_kv[KVROWS * 2 * INNER];
__device__ float g_ao[ROWS * INNER];
__device__ float g_wq_t [INNER * DIM];        // [n][k]
__device__ float g_wkv_t[2 * INNER * DIM_VIS];// [n][k]
__device__ float g_wout_t[DIM * INNER];       // [n][k]
__device__ float g_media_t[KVROWS * DIM_VIS];
__device__ int   g_qlist[BATCH][9][T_TXT];
__device__ int   g_qcount[BATCH][9];

__device__ __forceinline__ uint32_t f2tf32(float f) {
    uint32_t r;
    asm("cvt.rna.tf32.f32 %0, %1;" : "=r"(r) : "f"(f));
    return r;
}
__device__ __forceinline__ float rnd_tf32(float f) { return __uint_as_float(f2tf32(f)); }
__device__ __forceinline__ uint32_t smem_u32(const void* p) {
    uint32_t a;
    asm("{ .reg .u64 t; cvta.to.shared.u64 t, %1; cvt.u32.u64 %0, t; }" : "=r"(a) : "l"(p));
    return a;
}

#define CP_ASYNC16(dst, src) \
    asm volatile("cp.async.cg.shared.global [%0], [%1], 16;" :: "r"(dst), "l"(src))
#define CP_COMMIT() asm volatile("cp.async.commit_group;" ::: "memory")
#define CP_WAIT1()  asm volatile("cp.async.wait_group 1;" ::: "memory")
#define LDSM4(r0, r1, r2, r3, addr) \
    asm volatile("ldmatrix.sync.aligned.m8n8.x4.shared.b16 {%0,%1,%2,%3}, [%4];" \
        : "=r"(r0), "=r"(r1), "=r"(r2), "=r"(r3) : "r"(addr))

// ---------------- cp.async + ldmatrix pipelined TF32 GEMM ----------------
// C[M,N] = A[M,K] @ Bt[N,K]^T. Row-major fp32 pre-rounded to tf32.
// Block 128x128, KT=32, 256 threads (8 warps), warp tile 64x32, 3 stages.
#define KT 32
#define PR 36                              // floats per smem row (32 + 4 pad)
#define OP_BYTES (128 * PR * 4)            // 18432 per operand
#define STG (2 * OP_BYTES)                 // 36864 per stage
#define STAGES 3
#define SMEM_BYTES (STAGES * STG)          // 110592

__global__ __launch_bounds__(256) void tf32gemm_lm(const float* __restrict__ A,
                                                   const float* __restrict__ Bt,
                                                   float* __restrict__ C,
                                                   int M, int N, int K) {
    extern __shared__ char smem[];
    const uint32_t sb = smem_u32(smem);
    const int tid = threadIdx.x;
    const int lane = tid & 31, warp = tid >> 5;
    const int tq = lane & 3, tg = lane >> 2;
    const int wm = (warp >> 2) * 64;   // 0/64
    const int wn = (warp & 3) * 32;    // 0/32/64/96

    const int mblk = blockIdx.y * 128;
    const int nblk = blockIdx.x * 128;
    const float* Ab = A + (size_t)mblk * K;
    const float* Bb = Bt + (size_t)nblk * K;

    float acc[4][4][4];
    #pragma unroll
    for (int mf = 0; mf < 4; mf++)
        #pragma unroll
        for (int nf = 0; nf < 4; nf++)
            #pragma unroll
            for (int i = 0; i < 4; i++) acc[mf][nf][i] = 0.f;

    const int nK = K / KT;

    // both operand tiles: 128 rows x 8 16B-chunks
    auto issue = [&](int s, int c) {
        const uint32_t sa = sb + s * STG;
        const uint32_t sB = sa + OP_BYTES;
        const int k0 = c * KT;
        #pragma unroll
        for (int i = 0; i < 4; i++) {
            int id = tid + i * 256;             // 0..1023
            int row = id >> 3, c4 = id & 7;
            CP_ASYNC16(sa + row * (PR * 4) + c4 * 16,
                       Ab + (size_t)row * K + k0 + c4 * 4);
            CP_ASYNC16(sB + row * (PR * 4) + c4 * 16,
                       Bb + (size_t)row * K + k0 + c4 * 4);
        }
    };

    // ldmatrix per-lane byte offsets (within a stage)
    // A tile mf: 16x8 tf32 -> x4: rows m0+(lane&15), k col +4 if lane>=16
    uint32_t a_off[4], b_off[2];
    #pragma unroll
    for (int mf = 0; mf < 4; mf++)
        a_off[mf] = ((wm + mf * 16 + (lane & 15)) * PR + ((lane >> 4) * 4)) * 4;
    // B pair p covers nf=2p,2p+1: rows n0+(lane>>4)*8+(lane&7), k col +4 if (lane>>3)&1
    #pragma unroll
    for (int p = 0; p < 2; p++)
        b_off[p] = OP_BYTES +
            ((wn + p * 16 + ((lane >> 4) * 8) + (lane & 7)) * PR + (((lane >> 3) & 1) * 4)) * 4;

    issue(0, 0); CP_COMMIT();
    if (nK > 1) issue(1, 1);
    CP_COMMIT();

    int buf = 0;
    for (int c = 0; c < nK; c++) {
        CP_WAIT1();
        __syncthreads();
        if (c + 2 < nK) issue((c + 2) % STAGES, c + 2);
        CP_COMMIT();

        const uint32_t sbase = sb + buf * STG;

        #pragma unroll
        for (int ks = 0; ks < KT; ks += 8) {
            uint32_t af[4][4], bf[2][4];
            #pragma unroll
            for (int mf = 0; mf < 4; mf++)
                LDSM4(af[mf][0], af[mf][1], af[mf][2], af[mf][3],
                      sbase + a_off[mf] + ks * 4);
            #pragma unroll
            for (int p = 0; p < 2; p++)
                LDSM4(bf[p][0], bf[p][1], bf[p][2], bf[p][3],
                      sbase + b_off[p] + ks * 4);

            #pragma unroll
            for (int mf = 0; mf < 4; mf++)
                #pragma unroll
                for (int nf = 0; nf < 4; nf++) {
                    const uint32_t b0 = bf[nf >> 1][(nf & 1) * 2];
                    const uint32_t b1 = bf[nf >> 1][(nf & 1) * 2 + 1];
                    asm volatile(
                        "mma.sync.aligned.m16n8k8.row.col.f32.tf32.tf32.f32 "
                        "{%0,%1,%2,%3}, {%4,%5,%6,%7}, {%8,%9}, {%0,%1,%2,%3};"
                        : "+f"(acc[mf][nf][0]), "+f"(acc[mf][nf][1]),
                          "+f"(acc[mf][nf][2]), "+f"(acc[mf][nf][3])
                        : "r"(af[mf][0]), "r"(af[mf][1]), "r"(af[mf][2]), "r"(af[mf][3]),
                          "r"(b0), "r"(b1));
                }
        }
        __syncthreads();
        buf = (buf + 1) % STAGES;
    }

    // epilogue
    #pragma unroll
    for (int mf = 0; mf < 4; mf++) {
        const int row0 = mblk + wm + mf * 16 + tg;
        #pragma unroll
        for (int nf = 0; nf < 4; nf++) {
            const int col = nblk + wn + nf * 8 + 2 * tq;
            *(float2*)(C + (size_t)row0 * N + col) =
                make_float2(acc[mf][nf][0], acc[mf][nf][1]);
            *(float2*)(C + (size_t)(row0 + 8) * N + col) =
                make_float2(acc[mf][nf][2], acc[mf][nf][3]);
        }
    }
}

// ---------------- weight transpose [K][N] -> [N][K] + tf32 round ----------------
__global__ __launch_bounds__(256) void wtrans_kernel(const float* __restrict__ in,
                                                     float* __restrict__ out,
                                                     int K, int N) {
    __shared__ float t[32][33];
    const int k0 = blockIdx.y * 32, n0 = blockIdx.x * 32;
    const int tx = threadIdx.x & 31, ty = threadIdx.x >> 5;  // 32x8
    #pragma unroll
    for (int i = ty; i < 32; i += 8)
        t[i][tx] = in[(size_t)(k0 + i) * N + n0 + tx];
    __syncthreads();
    #pragma unroll
    for (int i = ty; i < 32; i += 8)
        out[(size_t)(n0 + i) * K + k0 + tx] = rnd_tf32(t[tx][i]);
}

// ---------------- tf32 pre-round (rna) for media ----------------
__global__ __launch_bounds__(256) void cvt_tf32_kernel(const float* __restrict__ in,
                                                       float* __restrict__ out, int n4) {
    int i = blockIdx.x * 256 + threadIdx.x;
    if (i < n4) {
        float4 v = ((const float4*)in)[i];
        v.x = rnd_tf32(v.x); v.y = rnd_tf32(v.y); v.z = rnd_tf32(v.z); v.w = rnd_tf32(v.w);
        ((float4*)out)[i] = v;
    }
}

// ---------------- LayerNorm (single pass, tf32-rounded output) ----------------
__global__ __launch_bounds__(256) void ln_kernel(const float* __restrict__ x,
                                                 const float* __restrict__ gamma,
                                                 const float* __restrict__ beta) {
    const int row = blockIdx.x;
    const float4* xr = (const float4*)(x + (size_t)row * DIM);
    float4* out = (float4*)(g_xn + (size_t)row * DIM);
    const int tid = threadIdx.x;

    __shared__ float reds[256], redq[256];
    float s = 0.f, sq = 0.f;
    #pragma unroll
    for (int c = tid; c < DIM / 4; c += 256) {
        float4 v = xr[c];
        s  += v.x + v.y + v.z + v.w;
        sq += v.x * v.x + v.y * v.y + v.z * v.z + v.w * v.w;
    }
    reds[tid] = s; redq[tid] = sq; __syncthreads();
    for (int o = 128; o > 0; o >>= 1) {
        if (tid < o) { reds[tid] += reds[tid + o]; redq[tid] += redq[tid + o]; }
        __syncthreads();
    }
    const float mu = reds[0] * (1.0f / DIM);
    const float var = redq[0] * (1.0f / DIM) - mu * mu;
    const float rstd = rsqrtf(var + LN_EPS);

    const float4* g4 = (const float4*)gamma;
    const float4* b4 = (const float4*)beta;
    #pragma unroll
    for (int c = tid; c < DIM / 4; c += 256) {
        float4 v = xr[c], g = g4[c], bb = b4[c], o4;
        o4.x = rnd_tf32((v.x - mu) * rstd * g.x + bb.x);
        o4.y = rnd_tf32((v.y - mu) * rstd * g.y + bb.y);
        o4.z = rnd_tf32((v.z - mu) * rstd * g.z + bb.z);
        o4.w = rnd_tf32((v.w - mu) * rstd * g.w + bb.w);
        out[c] = o4;
    }
}

// ---------------- parallel build of per-(b,tt) query lists ----------------
__global__ __launch_bounds__(256) void build_lists2(const int* __restrict__ locs) {
    const int b = blockIdx.x;
    const int tid = threadIdx.x;
    __shared__ int ssum[256];
    __shared__ int cnt[9];

    const int base = tid * 8;
    int v[8];
    int s = 0;
    #pragma unroll
    for (int j = 0; j < 8; j++) { v[j] = locs[b * T_TXT + base + j]; s += v[j]; }
    ssum[tid] = s;
    if (tid < 9) cnt[tid] = 0;
    __syncthreads();
    for (int off = 1; off < 256; off <<= 1) {
        int t = (tid >= off) ? ssum[tid - off] : 0;
        __syncthreads();
        ssum[tid] += t;
        __syncthreads();
    }
    int run = ssum[tid] - s;
    #pragma unroll
    for (int j = 0; j < 8; j++) {
        run += v[j];
        int p = atomicAdd(&cnt[run], 1);
        g_qlist[b][run][p] = base + j;
    }
    __syncthreads();
    if (tid < 9) g_qcount[b][tid] = cnt[tid];
}

// ---------------- masked chunk attention (tf32-rounded output) ----------------
__global__ __launch_bounds__(256) void attn_kernel() {
    const int blk = blockIdx.x;                 // b*72 + h*9 + tt
    const int b = blk / 72;
    const int h = (blk / 9) % 8;
    const int tt = blk % 9;
    const int cnt = g_qcount[b][tt];
    if (cnt == 0) return;

    const int lane = threadIdx.x & 31;
    const int warp = threadIdx.x >> 5;

    if (tt == 0) {
        for (int qi = warp; qi < cnt; qi += 8) {
            int i = g_qlist[b][0][qi];
            float* dst = g_ao + (size_t)(b * T_TXT + i) * INNER + h * DIM_HEAD;
            dst[lane] = 0.f; dst[lane + 32] = 0.f;
        }
        return;
    }

    __shared__ float ksh[64][65];
    __shared__ float vsh[64][65];
    const int base = b * 512 + (tt - 1) * 64;
    for (int idx = threadIdx.x; idx < 4096; idx += 256) {
        int r = idx >> 6, c = idx & 63;
        const float* kvr = g_kv + (size_t)(base + r) * (2 * INNER);
        ksh[r][c] = kvr[h * DIM_HEAD + c];
        vsh[r][c] = kvr[INNER + h * DIM_HEAD + c];
    }
    __syncthreads();

    const float scale = 0.125f;
    for (int qi = warp; qi < cnt; qi += 8) {
        const int i = g_qlist[b][tt][qi];
        const float* qr = g_q + (size_t)(b * T_TXT + i) * INNER + h * DIM_HEAD;
        const float q0 = qr[lane] * scale;
        const float q1 = qr[lane + 32] * scale;

        float s0 = 0.f, s1 = 0.f;
        #pragma unroll
        for (int d = 0; d < 32; d++) {
            float qd = __shfl_sync(0xffffffffu, q0, d);
            s0 += qd * ksh[lane][d];
            s1 += qd * ksh[lane + 32][d];
        }
        #pragma unroll
        for (int d = 0; d < 32; d++) {
            float qd = __shfl_sync(0xffffffffu, q1, d);
            s0 += qd * ksh[lane][d + 32];
            s1 += qd * ksh[lane + 32][d + 32];
        }
        float m = fmaxf(s0, s1);
        #pragma unroll
        for (int o = 16; o > 0; o >>= 1) m = fmaxf(m, __shfl_xor_sync(0xffffffffu, m, o));
        float p0 = __expf(s0 - m), p1 = __expf(s1 - m);
        float sum = p0 + p1;
        #pragma unroll
        for (int o = 16; o > 0; o >>= 1) sum += __shfl_xor_sync(0xffffffffu, sum, o);
        const float inv = 1.f / sum;
        p0 *= inv; p1 *= inv;

        float o0 = 0.f, o1 = 0.f;
        #pragma unroll
        for (int j = 0; j < 32; j++) {
            float pa = __shfl_sync(0xffffffffu, p0, j);
            float pb = __shfl_sync(0xffffffffu, p1, j);
            o0 += pa * vsh[j][lane]      + pb * vsh[j + 32][lane];
            o1 += pa * vsh[j][lane + 32] + pb * vsh[j + 32][lane + 32];
        }
        float* dst = g_ao + (size_t)(b * T_TXT + i) * INNER + h * DIM_HEAD;
        dst[lane]      = rnd_tf32(o0);
        dst[lane + 32] = rnd_tf32(o1);
    }
}

// ---------------- launch (q-GEMM kept in ncu's 4th slot) ----------------
extern "C" void kernel_launch(void* const* d_in, const int* in_sizes, int n_in,
                              void* d_out, int out_size) {
    const float* x     = (const float*)d_in[0];
    const float* media = (const float*)d_in[1];
    const int*   locs  = (const int*)d_in[2];
    const float* gamma = (const float*)d_in[3];
    const float* beta  = (const float*)d_in[4];
    const float* Wq    = (const float*)d_in[5];
    const float* Wkv   = (const float*)d_in[6];
    const float* Wout  = (const float*)d_in[7];
    float*       out   = (float*)d_out;

    float *p_xn, *p_q, *p_kv, *p_ao, *p_wq, *p_wkv, *p_wout, *p_media;
    cudaGetSymbolAddress((void**)&p_xn, g_xn);
    cudaGetSymbolAddress((void**)&p_q,  g_q);
    cudaGetSymbolAddress((void**)&p_kv, g_kv);
    cudaGetSymbolAddress((void**)&p_ao, g_ao);
    cudaGetSymbolAddress((void**)&p_wq, g_wq_t);
    cudaGetSymbolAddress((void**)&p_wkv, g_wkv_t);
    cudaGetSymbolAddress((void**)&p_wout, g_wout_t);
    cudaGetSymbolAddress((void**)&p_media, g_media_t);

    cudaFuncSetAttribute(tf32gemm_lm, cudaFuncAttributeMaxDynamicSharedMemorySize, SMEM_BYTES);

    // 1. Wq transpose+round
    wtrans_kernel<<<dim3(INNER / 32, DIM / 32), 256>>>(Wq, p_wq, DIM, INNER);
    // 2. LayerNorm
    ln_kernel<<<ROWS, 256>>>(x, gamma, beta);
    // 3. query grouping
    build_lists2<<<BATCH, 256>>>(locs);
    // 4. q = xn @ Wq             (8192 x 512 x 2048)  <-- profiled slot
    tf32gemm_lm<<<dim3(INNER / 128, ROWS / 128), 256, SMEM_BYTES>>>(
        p_xn, p_wq, p_q, ROWS, INNER, DIM);
    // 5-6. Wkv transpose + media round
    wtrans_kernel<<<dim3(2 * INNER / 32, DIM_VIS / 32), 256>>>(Wkv, p_wkv, DIM_VIS, 2 * INNER);
    cvt_tf32_kernel<<<(KVROWS * DIM_VIS / 4) / 256, 256>>>(media, p_media, KVROWS * DIM_VIS / 4);
    // 7. kv = media_flat @ Wkv   (2048 x 1024 x 1024)
    tf32gemm_lm<<<dim3((2 * INNER) / 128, KVROWS / 128), 256, SMEM_BYTES>>>(
        p_media, p_wkv, p_kv, KVROWS, 2 * INNER, DIM_VIS);
    // 8. masked chunk attention
    attn_kernel<<<BATCH * HEADS * 9, 256>>>();
    // 9. Wout transpose+round
    wtrans_kernel<<<dim3(DIM / 32, INNER / 32), 256>>>(Wout, p_wout, INNER, DIM);
    // 10. out = ao @ Wout        (8192 x 2048 x 512)
    tf32gemm_lm<<<dim3(DIM / 128, ROWS / 128), 256, SMEM_BYTES>>>(
        p_ao, p_wout, out, ROWS, DIM, INNER);
}

// round 12
// speedup vs baseline: 1.6602x; 1.0090x over previous
#include <cuda_runtime.h>
#include <cuda_bf16.h>
#include <cstdint>

// Problem constants
#define BATCH   4
#define T_TXT   2048
#define T_IMG   8
#define N_LAT   64
#define DIM     2048
#define DIM_VIS 1024
#define HEADS   8
#define DIM_HEAD 64
#define INNER   (HEADS * DIM_HEAD)      // 512
#define ROWS    (BATCH * T_TXT)         // 8192
#define KVROWS  (BATCH * T_IMG * N_LAT) // 2048
#define LN_EPS  1e-5f

// ---------------- scratch (static device, no allocs) ----------------
__device__ float g_xn[ROWS * DIM];
__device__ float g_q [ROWS * INNER];
__device__ float g_kv[KVROWS * 2 * INNER];
__device__ float g_ao[ROWS * INNER];
__device__ float g_wq_t [INNER * DIM];        // [n][k]
__device__ float g_wkv_t[2 * INNER * DIM_VIS];// [n][k]
__device__ float g_wout_t[DIM * INNER];       // [n][k]
__device__ float g_media_t[KVROWS * DIM_VIS];
__device__ int   g_qlist[BATCH][9][T_TXT];
__device__ int   g_qcount[BATCH][9];

__device__ __forceinline__ uint32_t f2tf32(float f) {
    uint32_t r;
    asm("cvt.rna.tf32.f32 %0, %1;" : "=r"(r) : "f"(f));
    return r;
}
__device__ __forceinline__ float rnd_tf32(float f) { return __uint_as_float(f2tf32(f)); }
__device__ __forceinline__ uint32_t smem_u32(const void* p) {
    uint32_t a;
    asm("{ .reg .u64 t; cvta.to.shared.u64 t, %1; cvt.u32.u64 %0, t; }" : "=r"(a) : "l"(p));
    return a;
}

#define CP_ASYNC16(dst, src) \
    asm volatile("cp.async.cg.shared.global [%0], [%1], 16;" :: "r"(dst), "l"(src))
#define CP_COMMIT() asm volatile("cp.async.commit_group;" ::: "memory")
#define CP_WAIT1()  asm volatile("cp.async.wait_group 1;" ::: "memory")
#define LDSM4(r0, r1, r2, r3, addr) \
    asm volatile("ldmatrix.sync.aligned.m8n8.x4.shared.b16 {%0,%1,%2,%3}, [%4];" \
        : "=r"(r0), "=r"(r1), "=r"(r2), "=r"(r3) : "r"(addr))

// ---------------- cp.async + ldmatrix pipelined TF32 GEMM ----------------
// C[M,N] = A[M,K] @ Bt[N,K]^T. Row-major fp32 pre-rounded to tf32.
// Block 128x128, KT=32, 128 threads (4 warps), warp tile 64x64, 3 stages.
#define KT 32
#define PR 36                              // floats per smem row (32 + 4 pad)
#define OP_BYTES (128 * PR * 4)            // 18432 per operand
#define STG (2 * OP_BYTES)                 // 36864 per stage
#define STAGES 3
#define SMEM_BYTES (STAGES * STG)          // 110592

__global__ __launch_bounds__(128) void tf32gemm_lm(const float* __restrict__ A,
                                                   const float* __restrict__ Bt,
                                                   float* __restrict__ C,
                                                   int M, int N, int K) {
    extern __shared__ char smem[];
    const uint32_t sb = smem_u32(smem);
    const int tid = threadIdx.x;
    const int lane = tid & 31, warp = tid >> 5;
    const int tq = lane & 3, tg = lane >> 2;
    const int wm = (warp >> 1) * 64;   // 0/64
    const int wn = (warp & 1) * 64;    // 0/64

    const int mblk = blockIdx.y * 128;
    const int nblk = blockIdx.x * 128;
    const float* Ab = A + (size_t)mblk * K;
    const float* Bb = Bt + (size_t)nblk * K;

    float acc[4][8][4];
    #pragma unroll
    for (int mf = 0; mf < 4; mf++)
        #pragma unroll
        for (int nf = 0; nf < 8; nf++)
            #pragma unroll
            for (int i = 0; i < 4; i++) acc[mf][nf][i] = 0.f;

    const int nK = K / KT;

    // both operand tiles: 128 rows x 8 16B-chunks; 2048 chunks / 128 threads = 16 each
    auto issue = [&](int s, int c) {
        const uint32_t sa = sb + s * STG;
        const uint32_t sB = sa + OP_BYTES;
        const int k0 = c * KT;
        #pragma unroll
        for (int i = 0; i < 8; i++) {
            int id = tid + i * 128;             // 0..1023
            int row = id >> 3, c4 = id & 7;
            CP_ASYNC16(sa + row * (PR * 4) + c4 * 16,
                       Ab + (size_t)row * K + k0 + c4 * 4);
            CP_ASYNC16(sB + row * (PR * 4) + c4 * 16,
                       Bb + (size_t)row * K + k0 + c4 * 4);
        }
    };

    // ldmatrix per-lane byte offsets (within a stage)
    uint32_t a_off[4], b_off[4];
    #pragma unroll
    for (int mf = 0; mf < 4; mf++)
        a_off[mf] = ((wm + mf * 16 + (lane & 15)) * PR + ((lane >> 4) * 4)) * 4;
    #pragma unroll
    for (int p = 0; p < 4; p++)
        b_off[p] = OP_BYTES +
            ((wn + p * 16 + ((lane >> 4) * 8) + (lane & 7)) * PR + (((lane >> 3) & 1) * 4)) * 4;

    issue(0, 0); CP_COMMIT();
    if (nK > 1) issue(1, 1);
    CP_COMMIT();

    int buf = 0;
    for (int c = 0; c < nK; c++) {
        CP_WAIT1();
        __syncthreads();
        if (c + 2 < nK) issue((c + 2) % STAGES, c + 2);
        CP_COMMIT();

        const uint32_t sbase = sb + buf * STG;

        #pragma unroll
        for (int ks = 0; ks < KT; ks += 8) {
            uint32_t af[4][4], bf[4][4];
            #pragma unroll
            for (int mf = 0; mf < 4; mf++)
                LDSM4(af[mf][0], af[mf][1], af[mf][2], af[mf][3],
                      sbase + a_off[mf] + ks * 4);
            #pragma unroll
            for (int p = 0; p < 4; p++)
                LDSM4(bf[p][0], bf[p][1], bf[p][2], bf[p][3],
                      sbase + b_off[p] + ks * 4);

            #pragma unroll
            for (int mf = 0; mf < 4; mf++)
                #pragma unroll
                for (int nf = 0; nf < 8; nf++) {
                    const uint32_t b0 = bf[nf >> 1][(nf & 1) * 2];
                    const uint32_t b1 = bf[nf >> 1][(nf & 1) * 2 + 1];
                    asm volatile(
                        "mma.sync.aligned.m16n8k8.row.col.f32.tf32.tf32.f32 "
                        "{%0,%1,%2,%3}, {%4,%5,%6,%7}, {%8,%9}, {%0,%1,%2,%3};"
                        : "+f"(acc[mf][nf][0]), "+f"(acc[mf][nf][1]),
                          "+f"(acc[mf][nf][2]), "+f"(acc[mf][nf][3])
                        : "r"(af[mf][0]), "r"(af[mf][1]), "r"(af[mf][2]), "r"(af[mf][3]),
                          "r"(b0), "r"(b1));
                }
        }
        __syncthreads();
        buf = (buf + 1) % STAGES;
    }

    // epilogue
    #pragma unroll
    for (int mf = 0; mf < 4; mf++) {
        const int row0 = mblk + wm + mf * 16 + tg;
        #pragma unroll
        for (int nf = 0; nf < 8; nf++) {
            const int col = nblk + wn + nf * 8 + 2 * tq;
            *(float2*)(C + (size_t)row0 * N + col) =
                make_float2(acc[mf][nf][0], acc[mf][nf][1]);
            *(float2*)(C + (size_t)(row0 + 8) * N + col) =
                make_float2(acc[mf][nf][2], acc[mf][nf][3]);
        }
    }
}

// ---------------- weight transpose [K][N] -> [N][K] + tf32 round ----------------
__global__ __launch_bounds__(256) void wtrans_kernel(const float* __restrict__ in,
                                                     float* __restrict__ out,
                                                     int K, int N) {
    __shared__ float t[32][33];
    const int k0 = blockIdx.y * 32, n0 = blockIdx.x * 32;
    const int tx = threadIdx.x & 31, ty = threadIdx.x >> 5;  // 32x8
    #pragma unroll
    for (int i = ty; i < 32; i += 8)
        t[i][tx] = in[(size_t)(k0 + i) * N + n0 + tx];
    __syncthreads();
    #pragma unroll
    for (int i = ty; i < 32; i += 8)
        out[(size_t)(n0 + i) * K + k0 + tx] = rnd_tf32(t[tx][i]);
}

// ---------------- tf32 pre-round (rna) for media ----------------
__global__ __launch_bounds__(256) void cvt_tf32_kernel(const float* __restrict__ in,
                                                       float* __restrict__ out, int n4) {
    int i = blockIdx.x * 256 + threadIdx.x;
    if (i < n4) {
        float4 v = ((const float4*)in)[i];
        v.x = rnd_tf32(v.x); v.y = rnd_tf32(v.y); v.z = rnd_tf32(v.z); v.w = rnd_tf32(v.w);
        ((float4*)out)[i] = v;
    }
}

// ---------------- LayerNorm (single pass, tf32-rounded output) ----------------
__global__ __launch_bounds__(256) void ln_kernel(const float* __restrict__ x,
                                                 const float* __restrict__ gamma,
                                                 const float* __restrict__ beta) {
    const int row = blockIdx.x;
    const float4* xr = (const float4*)(x + (size_t)row * DIM);
    float4* out = (float4*)(g_xn + (size_t)row * DIM);
    const int tid = threadIdx.x;

    __shared__ float reds[256], redq[256];
    float s = 0.f, sq = 0.f;
    #pragma unroll
    for (int c = tid; c < DIM / 4; c += 256) {
        float4 v = xr[c];
        s  += v.x + v.y + v.z + v.w;
        sq += v.x * v.x + v.y * v.y + v.z * v.z + v.w * v.w;
    }
    reds[tid] = s; redq[tid] = sq; __syncthreads();
    for (int o = 128; o > 0; o >>= 1) {
        if (tid < o) { reds[tid] += reds[tid + o]; redq[tid] += redq[tid + o]; }
        __syncthreads();
    }
    const float mu = reds[0] * (1.0f / DIM);
    const float var = redq[0] * (1.0f / DIM) - mu * mu;
    const float rstd = rsqrtf(var + LN_EPS);

    const float4* g4 = (const float4*)gamma;
    const float4* b4 = (const float4*)beta;
    #pragma unroll
    for (int c = tid; c < DIM / 4; c += 256) {
        float4 v = xr[c], g = g4[c], bb = b4[c], o4;
        o4.x = rnd_tf32((v.x - mu) * rstd * g.x + bb.x);
        o4.y = rnd_tf32((v.y - mu) * rstd * g.y + bb.y);
        o4.z = rnd_tf32((v.z - mu) * rstd * g.z + bb.z);
        o4.w = rnd_tf32((v.w - mu) * rstd * g.w + bb.w);
        out[c] = o4;
    }
}

// ---------------- parallel build of per-(b,tt) query lists ----------------
__global__ __launch_bounds__(256) void build_lists2(const int* __restrict__ locs) {
    const int b = blockIdx.x;
    const int tid = threadIdx.x;
    __shared__ int ssum[256];
    __shared__ int cnt[9];

    const int base = tid * 8;
    int v[8];
    int s = 0;
    #pragma unroll
    for (int j = 0; j < 8; j++) { v[j] = locs[b * T_TXT + base + j]; s += v[j]; }
    ssum[tid] = s;
    if (tid < 9) cnt[tid] = 0;
    __syncthreads();
    for (int off = 1; off < 256; off <<= 1) {
        int t = (tid >= off) ? ssum[tid - off] : 0;
        __syncthreads();
        ssum[tid] += t;
        __syncthreads();
    }
    int run = ssum[tid] - s;
    #pragma unroll
    for (int j = 0; j < 8; j++) {
        run += v[j];
        int p = atomicAdd(&cnt[run], 1);
        g_qlist[b][run][p] = base + j;
    }
    __syncthreads();
    if (tid < 9) g_qcount[b][tid] = cnt[tid];
}

// ---------------- masked chunk attention (tf32-rounded output) ----------------
__global__ __launch_bounds__(256) void attn_kernel() {
    const int blk = blockIdx.x;                 // b*72 + h*9 + tt
    const int b = blk / 72;
    const int h = (blk / 9) % 8;
    const int tt = blk % 9;
    const int cnt = g_qcount[b][tt];
    if (cnt == 0) return;

    const int lane = threadIdx.x & 31;
    const int warp = threadIdx.x >> 5;

    if (tt == 0) {
        for (int qi = warp; qi < cnt; qi += 8) {
            int i = g_qlist[b][0][qi];
            float* dst = g_ao + (size_t)(b * T_TXT + i) * INNER + h * DIM_HEAD;
            dst[lane] = 0.f; dst[lane + 32] = 0.f;
        }
        return;
    }

    __shared__ float ksh[64][65];
    __shared__ float vsh[64][65];
    const int base = b * 512 + (tt - 1) * 64;
    for (int idx = threadIdx.x; idx < 4096; idx += 256) {
        int r = idx >> 6, c = idx & 63;
        const float* kvr = g_kv + (size_t)(base + r) * (2 * INNER);
        ksh[r][c] = kvr[h * DIM_HEAD + c];
        vsh[r][c] = kvr[INNER + h * DIM_HEAD + c];
    }
    __syncthreads();

    const float scale = 0.125f;
    for (int qi = warp; qi < cnt; qi += 8) {
        const int i = g_qlist[b][tt][qi];
        const float* qr = g_q + (size_t)(b * T_TXT + i) * INNER + h * DIM_HEAD;
        const float q0 = qr[lane] * scale;
        const float q1 = qr[lane + 32] * scale;

        float s0 = 0.f, s1 = 0.f;
        #pragma unroll
        for (int d = 0; d < 32; d++) {
            float qd = __shfl_sync(0xffffffffu, q0, d);
            s0 += qd * ksh[lane][d];
            s1 += qd * ksh[lane + 32][d];
        }
        #pragma unroll
        for (int d = 0; d < 32; d++) {
            float qd = __shfl_sync(0xffffffffu, q1, d);
            s0 += qd * ksh[lane][d + 32];
            s1 += qd * ksh[lane + 32][d + 32];
        }
        float m = fmaxf(s0, s1);
        #pragma unroll
        for (int o = 16; o > 0; o >>= 1) m = fmaxf(m, __shfl_xor_sync(0xffffffffu, m, o));
        float p0 = __expf(s0 - m), p1 = __expf(s1 - m);
        float sum = p0 + p1;
        #pragma unroll
        for (int o = 16; o > 0; o >>= 1) sum += __shfl_xor_sync(0xffffffffu, sum, o);
        const float inv = 1.f / sum;
        p0 *= inv; p1 *= inv;

        float o0 = 0.f, o1 = 0.f;
        #pragma unroll
        for (int j = 0; j < 32; j++) {
            float pa = __shfl_sync(0xffffffffu, p0, j);
            float pb = __shfl_sync(0xffffffffu, p1, j);
            o0 += pa * vsh[j][lane]      + pb * vsh[j + 32][lane];
            o1 += pa * vsh[j][lane + 32] + pb * vsh[j + 32][lane + 32];
        }
        float* dst = g_ao + (size_t)(b * T_TXT + i) * INNER + h * DIM_HEAD;
        dst[lane]      = rnd_tf32(o0);
        dst[lane + 32] = rnd_tf32(o1);
    }
}

// ---------------- launch (q-GEMM kept in ncu's 4th slot) ----------------
extern "C" void kernel_launch(void* const* d_in, const int* in_sizes, int n_in,
                              void* d_out, int out_size) {
    const float* x     = (const float*)d_in[0];
    const float* media = (const float*)d_in[1];
    const int*   locs  = (const int*)d_in[2];
    const float* gamma = (const float*)d_in[3];
    const float* beta  = (const float*)d_in[4];
    const float* Wq    = (const float*)d_in[5];
    const float* Wkv   = (const float*)d_in[6];
    const float* Wout  = (const float*)d_in[7];
    float*       out   = (float*)d_out;

    float *p_xn, *p_q, *p_kv, *p_ao, *p_wq, *p_wkv, *p_wout, *p_media;
    cudaGetSymbolAddress((void**)&p_xn, g_xn);
    cudaGetSymbolAddress((void**)&p_q,  g_q);
    cudaGetSymbolAddress((void**)&p_kv, g_kv);
    cudaGetSymbolAddress((void**)&p_ao, g_ao);
    cudaGetSymbolAddress((void**)&p_wq, g_wq_t);
    cudaGetSymbolAddress((void**)&p_wkv, g_wkv_t);
    cudaGetSymbolAddress((void**)&p_wout, g_wout_t);
    cudaGetSymbolAddress((void**)&p_media, g_media_t);

    cudaFuncSetAttribute(tf32gemm_lm, cudaFuncAttributeMaxDynamicSharedMemorySize, SMEM_BYTES);

    // 1. Wq transpose+round
    wtrans_kernel<<<dim3(INNER / 32, DIM / 32), 256>>>(Wq, p_wq, DIM, INNER);
    // 2. LayerNorm
    ln_kernel<<<ROWS, 256>>>(x, gamma, beta);
    // 3. query grouping
    build_lists2<<<BATCH, 256>>>(locs);
    // 4. q = xn @ Wq             (8192 x 512 x 2048)  <-- profiled slot
    tf32gemm_lm<<<dim3(INNER / 128, ROWS / 128), 128, SMEM_BYTES>>>(
        p_xn, p_wq, p_q, ROWS, INNER, DIM);
    // 5-6. Wkv transpose + media round
    wtrans_kernel<<<dim3(2 * INNER / 32, DIM_VIS / 32), 256>>>(Wkv, p_wkv, DIM_VIS, 2 * INNER);
    cvt_tf32_kernel<<<(KVROWS * DIM_VIS / 4) / 256, 256>>>(media, p_media, KVROWS * DIM_VIS / 4);
    // 7. kv = media_flat @ Wkv   (2048 x 1024 x 1024)
    tf32gemm_lm<<<dim3((2 * INNER) / 128, KVROWS / 128), 128, SMEM_BYTES>>>(
        p_media, p_wkv, p_kv, KVROWS, 2 * INNER, DIM_VIS);
    // 8. masked chunk attention
    attn_kernel<<<BATCH * HEADS * 9, 256>>>();
    // 9. Wout transpose+round
    wtrans_kernel<<<dim3(DIM / 32, INNER / 32), 256>>>(Wout, p_wout, INNER, DIM);
    // 10. out = ao @ Wout        (8192 x 2048 x 512)
    tf32gemm_lm<<<dim3(DIM / 128, ROWS / 128), 128, SMEM_BYTES>>>(
        p_ao, p_wout, out, ROWS, DIM, INNER);
}

// round 13
// speedup vs baseline: 1.9117x; 1.1515x over previous
#include <cuda_runtime.h>
#include <cuda_bf16.h>
#include <cstdint>

// Problem constants
#define BATCH   4
#define T_TXT   2048
#define T_IMG   8
#define N_LAT   64
#define DIM     2048
#define DIM_VIS 1024
#define HEADS   8
#define DIM_HEAD 64
#define INNER   (HEADS * DIM_HEAD)      // 512
#define ROWS    (BATCH * T_TXT)         // 8192
#define KVROWS  (BATCH * T_IMG * N_LAT) // 2048
#define LN_EPS  1e-5f

// ---------------- scratch (static device, no allocs) ----------------
__device__ float g_xn[ROWS * DIM];
__device__ float g_q [ROWS * INNER];
__device__ float g_kv[KVROWS * 2 * INNER];
__device__ float g_ao[ROWS * INNER];
__device__ float g_wq_t [INNER * DIM];        // [n][k]
__device__ float g_wkv_t[2 * INNER * DIM_VIS];// [n][k]
__device__ float g_wout_t[DIM * INNER];       // [n][k]
__device__ float g_media_t[KVROWS * DIM_VIS];
__device__ int   g_qlist[BATCH][9][T_TXT];
__device__ int   g_qcount[BATCH][9];

__device__ __forceinline__ uint32_t f2tf32(float f) {
    uint32_t r;
    asm("cvt.rna.tf32.f32 %0, %1;" : "=r"(r) : "f"(f));
    return r;
}
__device__ __forceinline__ float rnd_tf32(float f) { return __uint_as_float(f2tf32(f)); }
__device__ __forceinline__ uint32_t smem_u32(const void* p) {
    uint32_t a;
    asm("{ .reg .u64 t; cvta.to.shared.u64 t, %1; cvt.u32.u64 %0, t; }" : "=r"(a) : "l"(p));
    return a;
}

#define CP_ASYNC16(dst, src) \
    asm volatile("cp.async.cg.shared.global [%0], [%1], 16;" :: "r"(dst), "l"(src))
#define CP_COMMIT() asm volatile("cp.async.commit_group;" ::: "memory")
#define CP_WAIT1()  asm volatile("cp.async.wait_group 1;" ::: "memory")
#define LDSM4(r0, r1, r2, r3, addr) \
    asm volatile("ldmatrix.sync.aligned.m8n8.x4.shared.b16 {%0,%1,%2,%3}, [%4];" \
        : "=r"(r0), "=r"(r1), "=r"(r2), "=r"(r3) : "r"(addr))

// ---------------- cp.async + ldmatrix pipelined TF32 GEMM ----------------
// C[M,N] = A[M,K] @ Bt[N,K]^T. Row-major fp32 pre-rounded to tf32.
// Block MTxd128, KT=32, MT threads (MT/32 warps), warp tile 64x64, 3 stages.
#define KT 32
#define PR 36                              // floats per smem row (32 + 4 pad)
#define STAGES 3

template<int MT>
__global__ __launch_bounds__(MT) void tf32gemm_lm(const float* __restrict__ A,
                                                  const float* __restrict__ Bt,
                                                  float* __restrict__ C,
                                                  int M, int N, int K) {
    constexpr int OP_A = MT * PR * 4;
    constexpr int OP_B = 128 * PR * 4;
    constexpr int STG  = OP_A + OP_B;
    extern __shared__ char smem[];
    const uint32_t sb = smem_u32(smem);
    const int tid = threadIdx.x;
    const int lane = tid & 31, warp = tid >> 5;
    const int tq = lane & 3, tg = lane >> 2;
    const int wm = (MT == 128) ? (warp >> 1) * 64 : 0;
    const int wn = (MT == 128) ? (warp & 1) * 64 : warp * 64;

    const int mblk = blockIdx.y * MT;
    const int nblk = blockIdx.x * 128;
    const float* Ab = A + (size_t)mblk * K;
    const float* Bb = Bt + (size_t)nblk * K;

    float acc[4][8][4];
    #pragma unroll
    for (int mf = 0; mf < 4; mf++)
        #pragma unroll
        for (int nf = 0; nf < 8; nf++)
            #pragma unroll
            for (int i = 0; i < 4; i++) acc[mf][nf][i] = 0.f;

    const int nK = K / KT;

    // A tile: MT rows x 8 chunks; B tile: 128 rows x 8 chunks
    auto issue = [&](int s, int c) {
        const uint32_t sa = sb + s * STG;
        const uint32_t sB = sa + OP_A;
        const int k0 = c * KT;
        constexpr int ITERS = (MT * 8 + 1024) / MT;
        #pragma unroll
        for (int i = 0; i < ITERS; i++) {
            int id = tid + i * MT;
            if (id < MT * 8) {
                int row = id >> 3, c4 = id & 7;
                CP_ASYNC16(sa + row * (PR * 4) + c4 * 16,
                           Ab + (size_t)row * K + k0 + c4 * 4);
            } else {
                int idB = id - MT * 8;
                int row = idB >> 3, c4 = idB & 7;
                CP_ASYNC16(sB + row * (PR * 4) + c4 * 16,
                           Bb + (size_t)row * K + k0 + c4 * 4);
            }
        }
    };

    uint32_t a_off[4], b_off[4];
    #pragma unroll
    for (int mf = 0; mf < 4; mf++)
        a_off[mf] = ((wm + mf * 16 + (lane & 15)) * PR + ((lane >> 4) * 4)) * 4;
    #pragma unroll
    for (int p = 0; p < 4; p++)
        b_off[p] = OP_A +
            ((wn + p * 16 + ((lane >> 4) * 8) + (lane & 7)) * PR + (((lane >> 3) & 1) * 4)) * 4;

    issue(0, 0); CP_COMMIT();
    if (nK > 1) issue(1, 1);
    CP_COMMIT();

    int buf = 0;
    for (int c = 0; c < nK; c++) {
        CP_WAIT1();
        __syncthreads();
        if (c + 2 < nK) issue((c + 2) % STAGES, c + 2);
        CP_COMMIT();

        const uint32_t sbase = sb + buf * STG;

        #pragma unroll
        for (int ks = 0; ks < KT; ks += 8) {
            uint32_t af[4][4], bf[4][4];
            #pragma unroll
            for (int mf = 0; mf < 4; mf++)
                LDSM4(af[mf][0], af[mf][1], af[mf][2], af[mf][3],
                      sbase + a_off[mf] + ks * 4);
            #pragma unroll
            for (int p = 0; p < 4; p++)
                LDSM4(bf[p][0], bf[p][1], bf[p][2], bf[p][3],
                      sbase + b_off[p] + ks * 4);

            #pragma unroll
            for (int mf = 0; mf < 4; mf++)
                #pragma unroll
                for (int nf = 0; nf < 8; nf++) {
                    const uint32_t b0 = bf[nf >> 1][(nf & 1) * 2];
                    const uint32_t b1 = bf[nf >> 1][(nf & 1) * 2 + 1];
                    asm volatile(
                        "mma.sync.aligned.m16n8k8.row.col.f32.tf32.tf32.f32 "
                        "{%0,%1,%2,%3}, {%4,%5,%6,%7}, {%8,%9}, {%0,%1,%2,%3};"
                        : "+f"(acc[mf][nf][0]), "+f"(acc[mf][nf][1]),
                          "+f"(acc[mf][nf][2]), "+f"(acc[mf][nf][3])
                        : "r"(af[mf][0]), "r"(af[mf][1]), "r"(af[mf][2]), "r"(af[mf][3]),
                          "r"(b0), "r"(b1));
                }
        }
        __syncthreads();
        buf = (buf + 1) % STAGES;
    }

    // epilogue
    #pragma unroll
    for (int mf = 0; mf < 4; mf++) {
        const int row0 = mblk + wm + mf * 16 + tg;
        #pragma unroll
        for (int nf = 0; nf < 8; nf++) {
            const int col = nblk + wn + nf * 8 + 2 * tq;
            *(float2*)(C + (size_t)row0 * N + col) =
                make_float2(acc[mf][nf][0], acc[mf][nf][1]);
            *(float2*)(C + (size_t)(row0 + 8) * N + col) =
                make_float2(acc[mf][nf][2], acc[mf][nf][3]);
        }
    }
}

#define SMEM128 (STAGES * (128 * PR * 4 + 128 * PR * 4))  // 110592
#define SMEM64  (STAGES * (64 * PR * 4 + 128 * PR * 4))   // 82944

// ---------------- weight transpose [K][N] -> [N][K] + tf32 round ----------------
__global__ __launch_bounds__(256) void wtrans_kernel(const float* __restrict__ in,
                                                     float* __restrict__ out,
                                                     int K, int N) {
    __shared__ float t[32][33];
    const int k0 = blockIdx.y * 32, n0 = blockIdx.x * 32;
    const int tx = threadIdx.x & 31, ty = threadIdx.x >> 5;  // 32x8
    #pragma unroll
    for (int i = ty; i < 32; i += 8)
        t[i][tx] = in[(size_t)(k0 + i) * N + n0 + tx];
    __syncthreads();
    #pragma unroll
    for (int i = ty; i < 32; i += 8)
        out[(size_t)(n0 + i) * K + k0 + tx] = rnd_tf32(t[tx][i]);
}

// ---------------- tf32 pre-round (rna) for media ----------------
__global__ __launch_bounds__(256) void cvt_tf32_kernel(const float* __restrict__ in,
                                                       float* __restrict__ out, int n4) {
    int i = blockIdx.x * 256 + threadIdx.x;
    if (i < n4) {
        float4 v = ((const float4*)in)[i];
        v.x = rnd_tf32(v.x); v.y = rnd_tf32(v.y); v.z = rnd_tf32(v.z); v.w = rnd_tf32(v.w);
        ((float4*)out)[i] = v;
    }
}

// ---------------- LayerNorm (single pass, tf32-rounded output) ----------------
__global__ __launch_bounds__(256) void ln_kernel(const float* __restrict__ x,
                                                 const float* __restrict__ gamma,
                                                 const float* __restrict__ beta) {
    const int row = blockIdx.x;
    const float4* xr = (const float4*)(x + (size_t)row * DIM);
    float4* out = (float4*)(g_xn + (size_t)row * DIM);
    const int tid = threadIdx.x;

    __shared__ float reds[256], redq[256];
    float s = 0.f, sq = 0.f;
    #pragma unroll
    for (int c = tid; c < DIM / 4; c += 256) {
        float4 v = xr[c];
        s  += v.x + v.y + v.z + v.w;
        sq += v.x * v.x + v.y * v.y + v.z * v.z + v.w * v.w;
    }
    reds[tid] = s; redq[tid] = sq; __syncthreads();
    for (int o = 128; o > 0; o >>= 1) {
        if (tid < o) { reds[tid] += reds[tid + o]; redq[tid] += redq[tid + o]; }
        __syncthreads();
    }
    const float mu = reds[0] * (1.0f / DIM);
    const float var = redq[0] * (1.0f / DIM) - mu * mu;
    const float rstd = rsqrtf(var + LN_EPS);

    const float4* g4 = (const float4*)gamma;
    const float4* b4 = (const float4*)beta;
    #pragma unroll
    for (int c = tid; c < DIM / 4; c += 256) {
        float4 v = xr[c], g = g4[c], bb = b4[c], o4;
        o4.x = rnd_tf32((v.x - mu) * rstd * g.x + bb.x);
        o4.y = rnd_tf32((v.y - mu) * rstd * g.y + bb.y);
        o4.z = rnd_tf32((v.z - mu) * rstd * g.z + bb.z);
        o4.w = rnd_tf32((v.w - mu) * rstd * g.w + bb.w);
        out[c] = o4;
    }
}

// ---------------- parallel build of per-(b,tt) query lists ----------------
__global__ __launch_bounds__(256) void build_lists2(const int* __restrict__ locs) {
    const int b = blockIdx.x;
    const int tid = threadIdx.x;
    __shared__ int ssum[256];
    __shared__ int cnt[9];

    const int base = tid * 8;
    int v[8];
    int s = 0;
    #pragma unroll
    for (int j = 0; j < 8; j++) { v[j] = locs[b * T_TXT + base + j]; s += v[j]; }
    ssum[tid] = s;
    if (tid < 9) cnt[tid] = 0;
    __syncthreads();
    for (int off = 1; off < 256; off <<= 1) {
        int t = (tid >= off) ? ssum[tid - off] : 0;
        __syncthreads();
        ssum[tid] += t;
        __syncthreads();
    }
    int run = ssum[tid] - s;
    #pragma unroll
    for (int j = 0; j < 8; j++) {
        run += v[j];
        int p = atomicAdd(&cnt[run], 1);
        g_qlist[b][run][p] = base + j;
    }
    __syncthreads();
    if (tid < 9) g_qcount[b][tid] = cnt[tid];
}

// ---------------- masked chunk attention (query-chunked grid) ----------------
#define QCHUNK 128
#define NCHUNK (T_TXT / QCHUNK)   // 16

__global__ __launch_bounds__(256) void attn_kernel() {
    const int blk = blockIdx.x;                 // b*72 + h*9 + tt
    const int b = blk / 72;
    const int h = (blk / 9) % 8;
    const int tt = blk % 9;
    const int start = blockIdx.y * QCHUNK;
    const int cnt = g_qcount[b][tt];
    if (start >= cnt) return;
    const int qend = min(cnt, start + QCHUNK);

    const int lane = threadIdx.x & 31;
    const int warp = threadIdx.x >> 5;

    if (tt == 0) {
        for (int qi = start + warp; qi < qend; qi += 8) {
            int i = g_qlist[b][0][qi];
            float* dst = g_ao + (size_t)(b * T_TXT + i) * INNER + h * DIM_HEAD;
            dst[lane] = 0.f; dst[lane + 32] = 0.f;
        }
        return;
    }

    __shared__ float ksh[64][65];
    __shared__ float vsh[64][65];
    const int base = b * 512 + (tt - 1) * 64;
    for (int idx = threadIdx.x; idx < 4096; idx += 256) {
        int r = idx >> 6, c = idx & 63;
        const float* kvr = g_kv + (size_t)(base + r) * (2 * INNER);
        ksh[r][c] = kvr[h * DIM_HEAD + c];
        vsh[r][c] = kvr[INNER + h * DIM_HEAD + c];
    }
    __syncthreads();

    const float scale = 0.125f;
    for (int qi = start + warp; qi < qend; qi += 8) {
        const int i = g_qlist[b][tt][qi];
        const float* qr = g_q + (size_t)(b * T_TXT + i) * INNER + h * DIM_HEAD;
        const float q0 = qr[lane] * scale;
        const float q1 = qr[lane + 32] * scale;

        float s0 = 0.f, s1 = 0.f;
        #pragma unroll
        for (int d = 0; d < 32; d++) {
            float qd = __shfl_sync(0xffffffffu, q0, d);
            s0 += qd * ksh[lane][d];
            s1 += qd * ksh[lane + 32][d];
        }
        #pragma unroll
        for (int d = 0; d < 32; d++) {
            float qd = __shfl_sync(0xffffffffu, q1, d);
            s0 += qd * ksh[lane][d + 32];
            s1 += qd * ksh[lane + 32][d + 32];
        }
        float m = fmaxf(s0, s1);
        #pragma unroll
        for (int o = 16; o > 0; o >>= 1) m = fmaxf(m, __shfl_xor_sync(0xffffffffu, m, o));
        float p0 = __expf(s0 - m), p1 = __expf(s1 - m);
        float sum = p0 + p1;
        #pragma unroll
        for (int o = 16; o > 0; o >>= 1) sum += __shfl_xor_sync(0xffffffffu, sum, o);
        const float inv = 1.f / sum;
        p0 *= inv; p1 *= inv;

        float o0 = 0.f, o1 = 0.f;
        #pragma unroll
        for (int j = 0; j < 32; j++) {
            float pa = __shfl_sync(0xffffffffu, p0, j);
            float pb = __shfl_sync(0xffffffffu, p1, j);
            o0 += pa * vsh[j][lane]      + pb * vsh[j + 32][lane];
            o1 += pa * vsh[j][lane + 32] + pb * vsh[j + 32][lane + 32];
        }
        float* dst = g_ao + (size_t)(b * T_TXT + i) * INNER + h * DIM_HEAD;
        dst[lane]      = rnd_tf32(o0);
        dst[lane + 32] = rnd_tf32(o1);
    }
}

// ---------------- launch (ln_kernel in ncu's 4th slot this round) ----------------
extern "C" void kernel_launch(void* const* d_in, const int* in_sizes, int n_in,
                              void* d_out, int out_size) {
    const float* x     = (const float*)d_in[0];
    const float* media = (const float*)d_in[1];
    const int*   locs  = (const int*)d_in[2];
    const float* gamma = (const float*)d_in[3];
    const float* beta  = (const float*)d_in[4];
    const float* Wq    = (const float*)d_in[5];
    const float* Wkv   = (const float*)d_in[6];
    const float* Wout  = (const float*)d_in[7];
    float*       out   = (float*)d_out;

    float *p_xn, *p_q, *p_kv, *p_ao, *p_wq, *p_wkv, *p_wout, *p_media;
    cudaGetSymbolAddress((void**)&p_xn, g_xn);
    cudaGetSymbolAddress((void**)&p_q,  g_q);
    cudaGetSymbolAddress((void**)&p_kv, g_kv);
    cudaGetSymbolAddress((void**)&p_ao, g_ao);
    cudaGetSymbolAddress((void**)&p_wq, g_wq_t);
    cudaGetSymbolAddress((void**)&p_wkv, g_wkv_t);
    cudaGetSymbolAddress((void**)&p_wout, g_wout_t);
    cudaGetSymbolAddress((void**)&p_media, g_media_t);

    cudaFuncSetAttribute(tf32gemm_lm<128>, cudaFuncAttributeMaxDynamicSharedMemorySize, SMEM128);
    cudaFuncSetAttribute(tf32gemm_lm<64>,  cudaFuncAttributeMaxDynamicSharedMemorySize, SMEM64);

    // 1. Wq transpose+round
    wtrans_kernel<<<dim3(INNER / 32, DIM / 32), 256>>>(Wq, p_wq, DIM, INNER);
    // 2. query grouping
    build_lists2<<<BATCH, 256>>>(locs);
    // 3. media round
    cvt_tf32_kernel<<<(KVROWS * DIM_VIS / 4) / 256, 256>>>(media, p_media, KVROWS * DIM_VIS / 4);
    // 4. LayerNorm   <-- profiled slot this round
    ln_kernel<<<ROWS, 256>>>(x, gamma, beta);
    // 5. q = xn @ Wq             (8192 x 512 x 2048)
    tf32gemm_lm<128><<<dim3(INNER / 128, ROWS / 128), 128, SMEM128>>>(
        p_xn, p_wq, p_q, ROWS, INNER, DIM);
    // 6. Wkv transpose+round
    wtrans_kernel<<<dim3(2 * INNER / 32, DIM_VIS / 32), 256>>>(Wkv, p_wkv, DIM_VIS, 2 * INNER);
    // 7. kv = media_flat @ Wkv   (2048 x 1024 x 1024), MT=64 -> 256 CTAs
    tf32gemm_lm<64><<<dim3((2 * INNER) / 128, KVROWS / 64), 64, SMEM64>>>(
        p_media, p_wkv, p_kv, KVROWS, 2 * INNER, DIM_VIS);
    // 8. masked chunk attention (query-chunked)
    attn_kernel<<<dim3(BATCH * HEADS * 9, NCHUNK), 256>>>();
    // 9. Wout transpose+round
    wtrans_kernel<<<dim3(DIM / 32, INNER / 32), 256>>>(Wout, p_wout, INNER, DIM);
    // 10. out = ao @ Wout        (8192 x 2048 x 512)
    tf32gemm_lm<128><<<dim3(DIM / 128, ROWS / 128), 128, SMEM128>>>(
        p_ao, p_wout, out, ROWS, DIM, INNER);
}

// round 14
// speedup vs baseline: 2.0095x; 1.0512x over previous
#include <cuda_runtime.h>
#include <cuda_bf16.h>
#include <cstdint>

// Problem constants
#define BATCH   4
#define T_TXT   2048
#define T_IMG   8
#define N_LAT   64
#define DIM     2048
#define DIM_VIS 1024
#define HEADS   8
#define DIM_HEAD 64
#define INNER   (HEADS * DIM_HEAD)      // 512
#define ROWS    (BATCH * T_TXT)         // 8192
#define KVROWS  (BATCH * T_IMG * N_LAT) // 2048
#define LN_EPS  1e-5f

// ---------------- scratch (static device, no allocs) ----------------
__device__ float g_xn[ROWS * DIM];
__device__ float g_q [ROWS * INNER];
__device__ float g_kv[KVROWS * 2 * INNER];
__device__ float g_ao[ROWS * INNER];
__device__ float g_wq_t [INNER * DIM];        // [n][k]
__device__ float g_wkv_t[2 * INNER * DIM_VIS];// [n][k]
__device__ float g_wout_t[DIM * INNER];       // [n][k]
__device__ float g_media_t[KVROWS * DIM_VIS];
__device__ int   g_qlist[BATCH][9][T_TXT];
__device__ int   g_qcount[BATCH][9];

__device__ __forceinline__ uint32_t f2tf32(float f) {
    uint32_t r;
    asm("cvt.rna.tf32.f32 %0, %1;" : "=r"(r) : "f"(f));
    return r;
}
__device__ __forceinline__ float rnd_tf32(float f) { return __uint_as_float(f2tf32(f)); }
__device__ __forceinline__ uint32_t smem_u32(const void* p) {
    uint32_t a;
    asm("{ .reg .u64 t; cvta.to.shared.u64 t, %1; cvt.u32.u64 %0, t; }" : "=r"(a) : "l"(p));
    return a;
}

#define CP_ASYNC16(dst, src) \
    asm volatile("cp.async.cg.shared.global [%0], [%1], 16;" :: "r"(dst), "l"(src))
#define CP_COMMIT() asm volatile("cp.async.commit_group;" ::: "memory")
#define CP_WAIT1()  asm volatile("cp.async.wait_group 1;" ::: "memory")
#define LDSM4(r0, r1, r2, r3, addr) \
    asm volatile("ldmatrix.sync.aligned.m8n8.x4.shared.b16 {%0,%1,%2,%3}, [%4];" \
        : "=r"(r0), "=r"(r1), "=r"(r2), "=r"(r3) : "r"(addr))

// ---------------- cp.async + ldmatrix pipelined TF32 GEMM ----------------
#define KT 32
#define PR 36                              // floats per smem row (32 + 4 pad)
#define STAGES 3

template<int MT>
__global__ __launch_bounds__(MT) void tf32gemm_lm(const float* __restrict__ A,
                                                  const float* __restrict__ Bt,
                                                  float* __restrict__ C,
                                                  int M, int N, int K) {
    constexpr int OP_A = MT * PR * 4;
    constexpr int OP_B = 128 * PR * 4;
    constexpr int STG  = OP_A + OP_B;
    extern __shared__ char smem[];
    const uint32_t sb = smem_u32(smem);
    const int tid = threadIdx.x;
    const int lane = tid & 31, warp = tid >> 5;
    const int tq = lane & 3, tg = lane >> 2;
    const int wm = (MT == 128) ? (warp >> 1) * 64 : 0;
    const int wn = (MT == 128) ? (warp & 1) * 64 : warp * 64;

    const int mblk = blockIdx.y * MT;
    const int nblk = blockIdx.x * 128;
    const float* Ab = A + (size_t)mblk * K;
    const float* Bb = Bt + (size_t)nblk * K;

    float acc[4][8][4];
    #pragma unroll
    for (int mf = 0; mf < 4; mf++)
        #pragma unroll
        for (int nf = 0; nf < 8; nf++)
            #pragma unroll
            for (int i = 0; i < 4; i++) acc[mf][nf][i] = 0.f;

    const int nK = K / KT;

    auto issue = [&](int s, int c) {
        const uint32_t sa = sb + s * STG;
        const uint32_t sB = sa + OP_A;
        const int k0 = c * KT;
        constexpr int ITERS = (MT * 8 + 1024) / MT;
        #pragma unroll
        for (int i = 0; i < ITERS; i++) {
            int id = tid + i * MT;
            if (id < MT * 8) {
                int row = id >> 3, c4 = id & 7;
                CP_ASYNC16(sa + row * (PR * 4) + c4 * 16,
                           Ab + (size_t)row * K + k0 + c4 * 4);
            } else {
                int idB = id - MT * 8;
                int row = idB >> 3, c4 = idB & 7;
                CP_ASYNC16(sB + row * (PR * 4) + c4 * 16,
                           Bb + (size_t)row * K + k0 + c4 * 4);
            }
        }
    };

    uint32_t a_off[4], b_off[4];
    #pragma unroll
    for (int mf = 0; mf < 4; mf++)
        a_off[mf] = ((wm + mf * 16 + (lane & 15)) * PR + ((lane >> 4) * 4)) * 4;
    #pragma unroll
    for (int p = 0; p < 4; p++)
        b_off[p] = OP_A +
            ((wn + p * 16 + ((lane >> 4) * 8) + (lane & 7)) * PR + (((lane >> 3) & 1) * 4)) * 4;

    issue(0, 0); CP_COMMIT();
    if (nK > 1) issue(1, 1);
    CP_COMMIT();

    int buf = 0;
    for (int c = 0; c < nK; c++) {
        CP_WAIT1();
        __syncthreads();
        if (c + 2 < nK) issue((c + 2) % STAGES, c + 2);
        CP_COMMIT();

        const uint32_t sbase = sb + buf * STG;

        #pragma unroll
        for (int ks = 0; ks < KT; ks += 8) {
            uint32_t af[4][4], bf[4][4];
            #pragma unroll
            for (int mf = 0; mf < 4; mf++)
                LDSM4(af[mf][0], af[mf][1], af[mf][2], af[mf][3],
                      sbase + a_off[mf] + ks * 4);
            #pragma unroll
            for (int p = 0; p < 4; p++)
                LDSM4(bf[p][0], bf[p][1], bf[p][2], bf[p][3],
                      sbase + b_off[p] + ks * 4);

            #pragma unroll
            for (int mf = 0; mf < 4; mf++)
                #pragma unroll
                for (int nf = 0; nf < 8; nf++) {
                    const uint32_t b0 = bf[nf >> 1][(nf & 1) * 2];
                    const uint32_t b1 = bf[nf >> 1][(nf & 1) * 2 + 1];
                    asm volatile(
                        "mma.sync.aligned.m16n8k8.row.col.f32.tf32.tf32.f32 "
                        "{%0,%1,%2,%3}, {%4,%5,%6,%7}, {%8,%9}, {%0,%1,%2,%3};"
                        : "+f"(acc[mf][nf][0]), "+f"(acc[mf][nf][1]),
                          "+f"(acc[mf][nf][2]), "+f"(acc[mf][nf][3])
                        : "r"(af[mf][0]), "r"(af[mf][1]), "r"(af[mf][2]), "r"(af[mf][3]),
                          "r"(b0), "r"(b1));
                }
        }
        __syncthreads();
        buf = (buf + 1) % STAGES;
    }

    #pragma unroll
    for (int mf = 0; mf < 4; mf++) {
        const int row0 = mblk + wm + mf * 16 + tg;
        #pragma unroll
        for (int nf = 0; nf < 8; nf++) {
            const int col = nblk + wn + nf * 8 + 2 * tq;
            *(float2*)(C + (size_t)row0 * N + col) =
                make_float2(acc[mf][nf][0], acc[mf][nf][1]);
            *(float2*)(C + (size_t)(row0 + 8) * N + col) =
                make_float2(acc[mf][nf][2], acc[mf][nf][3]);
        }
    }
}

#define SMEM128 (STAGES * (128 * PR * 4 + 128 * PR * 4))  // 110592
#define SMEM64  (STAGES * (64 * PR * 4 + 128 * PR * 4))   // 82944

// ---------------- weight transpose [K][N] -> [N][K] + tf32 round ----------------
__global__ __launch_bounds__(256) void wtrans_kernel(const float* __restrict__ in,
                                                     float* __restrict__ out,
                                                     int K, int N) {
    __shared__ float t[32][33];
    const int k0 = blockIdx.y * 32, n0 = blockIdx.x * 32;
    const int tx = threadIdx.x & 31, ty = threadIdx.x >> 5;  // 32x8
    #pragma unroll
    for (int i = ty; i < 32; i += 8)
        t[i][tx] = in[(size_t)(k0 + i) * N + n0 + tx];
    __syncthreads();
    #pragma unroll
    for (int i = ty; i < 32; i += 8)
        out[(size_t)(n0 + i) * K + k0 + tx] = rnd_tf32(t[tx][i]);
}

// ---------------- tf32 pre-round (rna) for media ----------------
__global__ __launch_bounds__(256) void cvt_tf32_kernel(const float* __restrict__ in,
                                                       float* __restrict__ out, int n4) {
    int i = blockIdx.x * 256 + threadIdx.x;
    if (i < n4) {
        float4 v = ((const float4*)in)[i];
        v.x = rnd_tf32(v.x); v.y = rnd_tf32(v.y); v.z = rnd_tf32(v.z); v.w = rnd_tf32(v.w);
        ((float4*)out)[i] = v;
    }
}

// ---------------- LayerNorm (single pass, tf32-rounded output) ----------------
__global__ __launch_bounds__(256) void ln_kernel(const float* __restrict__ x,
                                                 const float* __restrict__ gamma,
                                                 const float* __restrict__ beta) {
    const int row = blockIdx.x;
    const float4* xr = (const float4*)(x + (size_t)row * DIM);
    float4* out = (float4*)(g_xn + (size_t)row * DIM);
    const int tid = threadIdx.x;

    __shared__ float reds[256], redq[256];
    float s = 0.f, sq = 0.f;
    #pragma unroll
    for (int c = tid; c < DIM / 4; c += 256) {
        float4 v = xr[c];
        s  += v.x + v.y + v.z + v.w;
        sq += v.x * v.x + v.y * v.y + v.z * v.z + v.w * v.w;
    }
    reds[tid] = s; redq[tid] = sq; __syncthreads();
    for (int o = 128; o > 0; o >>= 1) {
        if (tid < o) { reds[tid] += reds[tid + o]; redq[tid] += redq[tid + o]; }
        __syncthreads();
    }
    const float mu = reds[0] * (1.0f / DIM);
    const float var = redq[0] * (1.0f / DIM) - mu * mu;
    const float rstd = rsqrtf(var + LN_EPS);

    const float4* g4 = (const float4*)gamma;
    const float4* b4 = (const float4*)beta;
    #pragma unroll
    for (int c = tid; c < DIM / 4; c += 256) {
        float4 v = xr[c], g = g4[c], bb = b4[c], o4;
        o4.x = rnd_tf32((v.x - mu) * rstd * g.x + bb.x);
        o4.y = rnd_tf32((v.y - mu) * rstd * g.y + bb.y);
        o4.z = rnd_tf32((v.z - mu) * rstd * g.z + bb.z);
        o4.w = rnd_tf32((v.w - mu) * rstd * g.w + bb.w);
        out[c] = o4;
    }
}

// ---------------- parallel build of per-(b,tt) query lists ----------------
__global__ __launch_bounds__(256) void build_lists2(const int* __restrict__ locs) {
    const int b = blockIdx.x;
    const int tid = threadIdx.x;
    __shared__ int ssum[256];
    __shared__ int cnt[9];

    const int base = tid * 8;
    int v[8];
    int s = 0;
    #pragma unroll
    for (int j = 0; j < 8; j++) { v[j] = locs[b * T_TXT + base + j]; s += v[j]; }
    ssum[tid] = s;
    if (tid < 9) cnt[tid] = 0;
    __syncthreads();
    for (int off = 1; off < 256; off <<= 1) {
        int t = (tid >= off) ? ssum[tid - off] : 0;
        __syncthreads();
        ssum[tid] += t;
        __syncthreads();
    }
    int run = ssum[tid] - s;
    #pragma unroll
    for (int j = 0; j < 8; j++) {
        run += v[j];
        int p = atomicAdd(&cnt[run], 1);
        g_qlist[b][run][p] = base + j;
    }
    __syncthreads();
    if (tid < 9) g_qcount[b][tid] = cnt[tid];
}

// ---------------- masked chunk attention (query-chunked grid) ----------------
#define QCHUNK 128
#define NCHUNK (T_TXT / QCHUNK)   // 16

__global__ __launch_bounds__(256) void attn_kernel() {
    const int blk = blockIdx.x;                 // b*72 + h*9 + tt
    const int b = blk / 72;
    const int h = (blk / 9) % 8;
    const int tt = blk % 9;
    const int start = blockIdx.y * QCHUNK;
    const int cnt = g_qcount[b][tt];
    if (start >= cnt) return;
    const int qend = min(cnt, start + QCHUNK);

    const int lane = threadIdx.x & 31;
    const int warp = threadIdx.x >> 5;

    if (tt == 0) {
        for (int qi = start + warp; qi < qend; qi += 8) {
            int i = g_qlist[b][0][qi];
            float* dst = g_ao + (size_t)(b * T_TXT + i) * INNER + h * DIM_HEAD;
            dst[lane] = 0.f; dst[lane + 32] = 0.f;
        }
        return;
    }

    __shared__ float ksh[64][65];
    __shared__ float vsh[64][65];
    const int base = b * 512 + (tt - 1) * 64;
    for (int idx = threadIdx.x; idx < 4096; idx += 256) {
        int r = idx >> 6, c = idx & 63;
        const float* kvr = g_kv + (size_t)(base + r) * (2 * INNER);
        ksh[r][c] = kvr[h * DIM_HEAD + c];
        vsh[r][c] = kvr[INNER + h * DIM_HEAD + c];
    }
    __syncthreads();

    const float scale = 0.125f;
    for (int qi = start + warp; qi < qend; qi += 8) {
        const int i = g_qlist[b][tt][qi];
        const float* qr = g_q + (size_t)(b * T_TXT + i) * INNER + h * DIM_HEAD;
        const float q0 = qr[lane] * scale;
        const float q1 = qr[lane + 32] * scale;

        float s0 = 0.f, s1 = 0.f;
        #pragma unroll
        for (int d = 0; d < 32; d++) {
            float qd = __shfl_sync(0xffffffffu, q0, d);
            s0 += qd * ksh[lane][d];
            s1 += qd * ksh[lane + 32][d];
        }
        #pragma unroll
        for (int d = 0; d < 32; d++) {
            float qd = __shfl_sync(0xffffffffu, q1, d);
            s0 += qd * ksh[lane][d + 32];
            s1 += qd * ksh[lane + 32][d + 32];
        }
        float m = fmaxf(s0, s1);
        #pragma unroll
        for (int o = 16; o > 0; o >>= 1) m = fmaxf(m, __shfl_xor_sync(0xffffffffu, m, o));
        float p0 = __expf(s0 - m), p1 = __expf(s1 - m);
        float sum = p0 + p1;
        #pragma unroll
        for (int o = 16; o > 0; o >>= 1) sum += __shfl_xor_sync(0xffffffffu, sum, o);
        const float inv = 1.f / sum;
        p0 *= inv; p1 *= inv;

        float o0 = 0.f, o1 = 0.f;
        #pragma unroll
        for (int j = 0; j < 32; j++) {
            float pa = __shfl_sync(0xffffffffu, p0, j);
            float pb = __shfl_sync(0xffffffffu, p1, j);
            o0 += pa * vsh[j][lane]      + pb * vsh[j + 32][lane];
            o1 += pa * vsh[j][lane + 32] + pb * vsh[j + 32][lane + 32];
        }
        float* dst = g_ao + (size_t)(b * T_TXT + i) * INNER + h * DIM_HEAD;
        dst[lane]      = rnd_tf32(o0);
        dst[lane + 32] = rnd_tf32(o1);
    }
}

// ---------------- launch (stream-parallel DAG; kv-GEMM in ncu's 4th slot) ----------------
extern "C" void kernel_launch(void* const* d_in, const int* in_sizes, int n_in,
                              void* d_out, int out_size) {
    const float* x     = (const float*)d_in[0];
    const float* media = (const float*)d_in[1];
    const int*   locs  = (const int*)d_in[2];
    const float* gamma = (const float*)d_in[3];
    const float* beta  = (const float*)d_in[4];
    const float* Wq    = (const float*)d_in[5];
    const float* Wkv   = (const float*)d_in[6];
    const float* Wout  = (const float*)d_in[7];
    float*       out   = (float*)d_out;

    float *p_xn, *p_q, *p_kv, *p_ao, *p_wq, *p_wkv, *p_wout, *p_media;
    cudaGetSymbolAddress((void**)&p_xn, g_xn);
    cudaGetSymbolAddress((void**)&p_q,  g_q);
    cudaGetSymbolAddress((void**)&p_kv, g_kv);
    cudaGetSymbolAddress((void**)&p_ao, g_ao);
    cudaGetSymbolAddress((void**)&p_wq, g_wq_t);
    cudaGetSymbolAddress((void**)&p_wkv, g_wkv_t);
    cudaGetSymbolAddress((void**)&p_wout, g_wout_t);
    cudaGetSymbolAddress((void**)&p_media, g_media_t);

    cudaFuncSetAttribute(tf32gemm_lm<128>, cudaFuncAttributeMaxDynamicSharedMemorySize, SMEM128);
    cudaFuncSetAttribute(tf32gemm_lm<64>,  cudaFuncAttributeMaxDynamicSharedMemorySize, SMEM64);

    // one-time stream/event setup (identical work on every call -> deterministic)
    static cudaStream_t s1 = nullptr, s2 = nullptr;
    static cudaEvent_t eFork = nullptr, eKv = nullptr, eBl = nullptr, eWout = nullptr;
    if (s1 == nullptr) {
        cudaStreamCreateWithFlags(&s1, cudaStreamNonBlocking);
        cudaStreamCreateWithFlags(&s2, cudaStreamNonBlocking);
        cudaEventCreateWithFlags(&eFork, cudaEventDisableTiming);
        cudaEventCreateWithFlags(&eKv,   cudaEventDisableTiming);
        cudaEventCreateWithFlags(&eBl,   cudaEventDisableTiming);
        cudaEventCreateWithFlags(&eWout, cudaEventDisableTiming);
    }

    // fork side streams from the main (captured) stream
    cudaEventRecord(eFork, 0);
    cudaStreamWaitEvent(s1, eFork, 0);
    cudaStreamWaitEvent(s2, eFork, 0);

    // main chain: Wq-trans -> ln -> q-GEMM
    wtrans_kernel<<<dim3(INNER / 32, DIM / 32), 256>>>(Wq, p_wq, DIM, INNER);

    // side chain s1: Wkv-trans -> media-cvt -> kv-GEMM
    wtrans_kernel<<<dim3(2 * INNER / 32, DIM_VIS / 32), 256, 0, s1>>>(Wkv, p_wkv, DIM_VIS, 2 * INNER);
    cvt_tf32_kernel<<<(KVROWS * DIM_VIS / 4) / 256, 256, 0, s1>>>(media, p_media, KVROWS * DIM_VIS / 4);
    tf32gemm_lm<64><<<dim3((2 * INNER) / 128, KVROWS / 64), 64, SMEM64, s1>>>(  // 4th launch: profiled
        p_media, p_wkv, p_kv, KVROWS, 2 * INNER, DIM_VIS);
    cudaEventRecord(eKv, s1);

    // side chain s2: build_lists ; Wout-trans
    build_lists2<<<BATCH, 256, 0, s2>>>(locs);
    cudaEventRecord(eBl, s2);
    wtrans_kernel<<<dim3(DIM / 32, INNER / 32), 256, 0, s2>>>(Wout, p_wout, INNER, DIM);
    cudaEventRecord(eWout, s2);

    // main chain continues
    ln_kernel<<<ROWS, 256>>>(x, gamma, beta);
    tf32gemm_lm<128><<<dim3(INNER / 128, ROWS / 128), 128, SMEM128>>>(
        p_xn, p_wq, p_q, ROWS, INNER, DIM);

    // join: attn needs q (main), kv (s1), lists (s2)
    cudaStreamWaitEvent(0, eKv, 0);
    cudaStreamWaitEvent(0, eBl, 0);
    attn_kernel<<<dim3(BATCH * HEADS * 9, NCHUNK), 256>>>();

    // out-GEMM needs attn (main) + Wout-trans (s2)
    cudaStreamWaitEvent(0, eWout, 0);
    tf32gemm_lm<128><<<dim3(DIM / 128, ROWS / 128), 128, SMEM128>>>(
        p_ao, p_wout, out, ROWS, DIM, INNER);
}